// round 3
// baseline (speedup 1.0000x reference)
#include <cuda_runtime.h>
#include <math.h>

#define C_DIM  1024
#define D_HEAD 64
#define B_SZ   4
#define T_LEN  4096
#define M_ROWS (B_SZ * T_LEN)

// Scratch for projected q, k, v: [B, T, 64] each (4 MB each)
__device__ float g_q[M_ROWS * D_HEAD];
__device__ float g_k[M_ROWS * D_HEAD];
__device__ float g_v[M_ROWS * D_HEAD];

// ---------------------------------------------------------------------------
// Projection GEMM: out[m, n] = X[m, :] @ W[:, n] + bias[n]
// M = 16384, K = 1024, N = 64.  Tile: 64x64, BK = 16, 256 threads, 4x4/thread.
// blockIdx.y selects which projection (0:q 1:k 2:v).
// ---------------------------------------------------------------------------
__global__ __launch_bounds__(256) void proj_kernel(
    const float* __restrict__ Xq, const float* __restrict__ Xk, const float* __restrict__ Xv,
    const float* __restrict__ Wq, const float* __restrict__ bq,
    const float* __restrict__ Wk, const float* __restrict__ bk,
    const float* __restrict__ Wv, const float* __restrict__ bv)
{
    __shared__ float As[16][65];   // [k][m], padded
    __shared__ float Bs[16][64];   // [k][n]

    const float* X; const float* W; const float* bias; float* out;
    if (blockIdx.y == 0)      { X = Xq; W = Wq; bias = bq; out = g_q; }
    else if (blockIdx.y == 1) { X = Xk; W = Wk; bias = bk; out = g_k; }
    else                      { X = Xv; W = Wv; bias = bv; out = g_v; }

    const int t   = threadIdx.x;
    const int tx  = t & 15;        // 0..15 -> 4 output cols
    const int ty  = t >> 4;        // 0..15 -> 4 output rows
    const int m0  = blockIdx.x * 64;

    const int arow = t >> 2;          // 0..63
    const int akq  = (t & 3) << 2;    // 0,4,8,12
    const int bkr  = t >> 4;          // 0..15
    const int bcol = (t & 15) << 2;   // 0..60

    float acc[4][4] = {};

    for (int k0 = 0; k0 < C_DIM; k0 += 16) {
        float4 av = *(const float4*)(X + (size_t)(m0 + arow) * C_DIM + k0 + akq);
        As[akq + 0][arow] = av.x;
        As[akq + 1][arow] = av.y;
        As[akq + 2][arow] = av.z;
        As[akq + 3][arow] = av.w;
        float4 wv = *(const float4*)(W + (size_t)(k0 + bkr) * D_HEAD + bcol);
        *(float4*)&Bs[bkr][bcol] = wv;
        __syncthreads();

        #pragma unroll
        for (int kk = 0; kk < 16; kk++) {
            float a[4];
            #pragma unroll
            for (int i = 0; i < 4; i++) a[i] = As[kk][ty * 4 + i];
            float4 bv4 = *(const float4*)&Bs[kk][tx * 4];
            float b[4] = {bv4.x, bv4.y, bv4.z, bv4.w};
            #pragma unroll
            for (int i = 0; i < 4; i++)
                #pragma unroll
                for (int j = 0; j < 4; j++)
                    acc[i][j] = fmaf(a[i], b[j], acc[i][j]);
        }
        __syncthreads();
    }

    #pragma unroll
    for (int i = 0; i < 4; i++) {
        #pragma unroll
        for (int j = 0; j < 4; j++) {
            out[(size_t)(m0 + ty * 4 + i) * D_HEAD + tx * 4 + j] =
                acc[i][j] + bias[tx * 4 + j];
        }
    }
}

// ---------------------------------------------------------------------------
// Flash attention (fp32): one block per (batch, 64-row q tile).
// 256 threads; thread (ty,tx) owns a 4x4 register tile of S/P and O.
// Online softmax via 16-lane shuffle reductions (row group = same ty).
// P is bounced through the k_s buffer between the two GEMMs.
// Tile loads: each thread loads 16 floats = row (t>>2), cols (t&3)*16..+15.
// ---------------------------------------------------------------------------
__global__ __launch_bounds__(256) void attn_kernel(float* __restrict__ out)
{
    __shared__ float q_s[D_HEAD * 64];   // [d][r]  (transposed, pre-scaled)
    __shared__ float k_s[D_HEAD * 64];   // [d][c]; reused as P[r][c]
    __shared__ float v_s[64 * D_HEAD];   // [s][c]

    const int b  = blockIdx.y;
    const int qi = (gridDim.x - 1) - blockIdx.x;   // long blocks launch first

    const float* qb = g_q + ((size_t)b * T_LEN + qi * 64) * D_HEAD;
    const float* kb = g_k + (size_t)b * T_LEN * D_HEAD;
    const float* vb = g_v + (size_t)b * T_LEN * D_HEAD;

    const int t    = threadIdx.x;
    const int tx   = t & 15;
    const int ty   = t >> 4;
    const int r0   = ty * 4;
    const int c0   = tx * 4;
    const int lrow = t >> 2;          // 0..63
    const int lc0  = (t & 3) * 16;    // 0,16,32,48 — 16 cols per thread

    // Load q tile transposed, scaled by 1/sqrt(64)
    {
        const float sc = 0.125f;
        #pragma unroll
        for (int u = 0; u < 4; u++) {
            const int lcol = lc0 + u * 4;
            float4 qv = *(const float4*)(qb + lrow * D_HEAD + lcol);
            q_s[(lcol + 0) * 64 + lrow] = qv.x * sc;
            q_s[(lcol + 1) * 64 + lrow] = qv.y * sc;
            q_s[(lcol + 2) * 64 + lrow] = qv.z * sc;
            q_s[(lcol + 3) * 64 + lrow] = qv.w * sc;
        }
    }

    float O[4][4] = {};
    float m_i[4] = {-1e30f, -1e30f, -1e30f, -1e30f};
    float l_i[4] = {};

    for (int j = 0; j <= qi; j++) {
        __syncthreads();   // previous iter's P/V reads done; q_s visible on iter 0

        // Load k tile transposed [d][c], v tile natural [s][c]
        #pragma unroll
        for (int u = 0; u < 4; u++) {
            const int lcol = lc0 + u * 4;
            float4 kv = *(const float4*)(kb + (size_t)(j * 64 + lrow) * D_HEAD + lcol);
            k_s[(lcol + 0) * 64 + lrow] = kv.x;
            k_s[(lcol + 1) * 64 + lrow] = kv.y;
            k_s[(lcol + 2) * 64 + lrow] = kv.z;
            k_s[(lcol + 3) * 64 + lrow] = kv.w;
            float4 vv = *(const float4*)(vb + (size_t)(j * 64 + lrow) * D_HEAD + lcol);
            *(float4*)&v_s[lrow * 64 + lcol] = vv;
        }
        __syncthreads();

        // S = q_tile @ k_tile^T  (4x4 per thread)
        float S[4][4] = {};
        #pragma unroll 8
        for (int d = 0; d < D_HEAD; d++) {
            float4 aa = *(const float4*)&q_s[d * 64 + r0];
            float4 bb = *(const float4*)&k_s[d * 64 + c0];
            float a[4] = {aa.x, aa.y, aa.z, aa.w};
            float bv[4] = {bb.x, bb.y, bb.z, bb.w};
            #pragma unroll
            for (int ii = 0; ii < 4; ii++)
                #pragma unroll
                for (int jj = 0; jj < 4; jj++)
                    S[ii][jj] = fmaf(a[ii], bv[jj], S[ii][jj]);
        }

        // Causal mask on the diagonal tile
        if (j == qi) {
            #pragma unroll
            for (int ii = 0; ii < 4; ii++)
                #pragma unroll
                for (int jj = 0; jj < 4; jj++)
                    if (c0 + jj > r0 + ii) S[ii][jj] = -1e30f;
        }

        // Online softmax (row groups = 16 lanes sharing ty; xor offsets < 16
        // stay inside the half-warp, so full-mask shuffles are safe)
        #pragma unroll
        for (int ii = 0; ii < 4; ii++) {
            float mx = fmaxf(fmaxf(S[ii][0], S[ii][1]), fmaxf(S[ii][2], S[ii][3]));
            #pragma unroll
            for (int off = 8; off >= 1; off >>= 1)
                mx = fmaxf(mx, __shfl_xor_sync(0xffffffffu, mx, off));
            float m_new = fmaxf(m_i[ii], mx);
            float ssum = 0.f;
            #pragma unroll
            for (int jj = 0; jj < 4; jj++) {
                float p = __expf(S[ii][jj] - m_new);
                S[ii][jj] = p;
                ssum += p;
            }
            #pragma unroll
            for (int off = 8; off >= 1; off >>= 1)
                ssum += __shfl_xor_sync(0xffffffffu, ssum, off);
            float alpha = __expf(m_i[ii] - m_new);
            l_i[ii] = l_i[ii] * alpha + ssum;
            m_i[ii] = m_new;
            #pragma unroll
            for (int jj = 0; jj < 4; jj++) O[ii][jj] *= alpha;
        }

        __syncthreads();   // everyone done reading k_s (S GEMM)

        // Stash P into k_s as [r][c]
        #pragma unroll
        for (int ii = 0; ii < 4; ii++)
            *(float4*)&k_s[(r0 + ii) * 64 + c0] =
                make_float4(S[ii][0], S[ii][1], S[ii][2], S[ii][3]);

        __syncthreads();

        // O += P @ V
        #pragma unroll 8
        for (int s = 0; s < 64; s++) {
            float a[4];
            #pragma unroll
            for (int ii = 0; ii < 4; ii++) a[ii] = k_s[(r0 + ii) * 64 + s];
            float4 bb = *(const float4*)&v_s[s * 64 + c0];
            float bv[4] = {bb.x, bb.y, bb.z, bb.w};
            #pragma unroll
            for (int ii = 0; ii < 4; ii++)
                #pragma unroll
                for (int jj = 0; jj < 4; jj++)
                    O[ii][jj] = fmaf(a[ii], bv[jj], O[ii][jj]);
        }
    }

    // Epilogue: divide by row sums and store
    float* ob = out + ((size_t)b * T_LEN + qi * 64) * D_HEAD;
    #pragma unroll
    for (int ii = 0; ii < 4; ii++) {
        float inv = 1.0f / l_i[ii];
        #pragma unroll
        for (int jj = 0; jj < 4; jj++)
            ob[(r0 + ii) * D_HEAD + c0 + jj] = O[ii][jj] * inv;
    }
}

// ---------------------------------------------------------------------------
extern "C" void kernel_launch(void* const* d_in, const int* in_sizes, int n_in,
                              void* d_out, int out_size)
{
    (void)in_sizes; (void)n_in; (void)out_size;
    const float* Q  = (const float*)d_in[0];
    const float* K  = (const float*)d_in[1];
    const float* V  = (const float*)d_in[2];
    const float* Wq = (const float*)d_in[3];
    const float* bq = (const float*)d_in[4];
    const float* Wk = (const float*)d_in[5];
    const float* bk = (const float*)d_in[6];
    const float* Wv = (const float*)d_in[7];
    const float* bv = (const float*)d_in[8];

    dim3 pg(M_ROWS / 64, 3);
    proj_kernel<<<pg, 256>>>(Q, K, V, Wq, bq, Wk, bk, Wv, bv);

    dim3 ag(T_LEN / 64, B_SZ);
    attn_kernel<<<ag, 256>>>((float*)d_out);
}

// round 4
// speedup vs baseline: 3.1499x; 3.1499x over previous
#include <cuda_runtime.h>
#include <stdint.h>
#include <math.h>

#define C_DIM  1024
#define D_HEAD 64
#define B_SZ   4
#define T_LEN  4096
#define M_ROWS (B_SZ * T_LEN)

// Scratch for projected q, k, v
__device__ float g_q[M_ROWS * D_HEAD];
__device__ float g_k[M_ROWS * D_HEAD];
__device__ float g_v[M_ROWS * D_HEAD];

__device__ __forceinline__ uint32_t f2tf(float x) {
    uint32_t r; asm("cvt.rna.tf32.f32 %0, %1;" : "=r"(r) : "f"(x)); return r;
}
__device__ __forceinline__ uint32_t fb(float x) { return __float_as_uint(x); }

__device__ __forceinline__ void mma_tf32(float c[4],
    uint32_t a0, uint32_t a1, uint32_t a2, uint32_t a3,
    uint32_t b0, uint32_t b1)
{
    asm volatile(
        "mma.sync.aligned.m16n8k8.row.col.f32.tf32.tf32.f32 "
        "{%0,%1,%2,%3}, {%4,%5,%6,%7}, {%8,%9}, {%0,%1,%2,%3};"
        : "+f"(c[0]), "+f"(c[1]), "+f"(c[2]), "+f"(c[3])
        : "r"(a0), "r"(a1), "r"(a2), "r"(a3), "r"(b0), "r"(b1));
}

// ---------------------------------------------------------------------------
// Projection GEMM (tf32 MMA): out[m,n] = X[m,:] @ W[:,n] + bias[n]
// M=16384, K=1024, N=64. CTA = 128 rows; 8 warps, warp tile 16x64.
// K-loop step 32, register double-buffered gmem prefetch.
// blockIdx.y: 0=q 1=k 2=v.
// ---------------------------------------------------------------------------
#define XS_STRIDE 40
#define WS_STRIDE 72

__global__ __launch_bounds__(256) void proj_kernel(
    const float* __restrict__ Xq, const float* __restrict__ Xk, const float* __restrict__ Xv,
    const float* __restrict__ Wq, const float* __restrict__ bq,
    const float* __restrict__ Wk, const float* __restrict__ bk,
    const float* __restrict__ Wv, const float* __restrict__ bv)
{
    __shared__ float Xs[128][XS_STRIDE];  // [m][k], tf32 bits
    __shared__ float Ws[32][WS_STRIDE];   // [k][n], tf32 bits

    const float* X; const float* W; const float* bias; float* out;
    if (blockIdx.y == 0)      { X = Xq; W = Wq; bias = bq; out = g_q; }
    else if (blockIdx.y == 1) { X = Xk; W = Wk; bias = bk; out = g_k; }
    else                      { X = Xv; W = Wv; bias = bv; out = g_v; }

    const int t    = threadIdx.x;
    const int lane = t & 31;
    const int w    = t >> 5;          // warp 0..7
    const int g    = lane >> 2;       // 0..7
    const int tig  = lane & 3;        // 0..3
    const int m0   = blockIdx.x * 128;

    const int xrow = t >> 1;          // 0..127
    const int xc0  = (t & 1) * 16;    // 0 or 16
    const int wrow = t >> 3;          // 0..31
    const int wc0  = (t & 7) * 8;     // 0..56

    // Prefetch step 0
    float4 xv[4], wv[2];
    #pragma unroll
    for (int i = 0; i < 4; i++)
        xv[i] = *(const float4*)(X + (size_t)(m0 + xrow) * C_DIM + xc0 + 4 * i);
    #pragma unroll
    for (int i = 0; i < 2; i++)
        wv[i] = *(const float4*)(W + (size_t)wrow * D_HEAD + wc0 + 4 * i);

    float c[8][4] = {};

    for (int k0 = 0; k0 < C_DIM; k0 += 32) {
        // Store prefetched tile (cvt to tf32)
        #pragma unroll
        for (int i = 0; i < 4; i++) {
            Xs[xrow][xc0 + 4*i + 0] = __uint_as_float(f2tf(xv[i].x));
            Xs[xrow][xc0 + 4*i + 1] = __uint_as_float(f2tf(xv[i].y));
            Xs[xrow][xc0 + 4*i + 2] = __uint_as_float(f2tf(xv[i].z));
            Xs[xrow][xc0 + 4*i + 3] = __uint_as_float(f2tf(xv[i].w));
        }
        #pragma unroll
        for (int i = 0; i < 2; i++) {
            Ws[wrow][wc0 + 4*i + 0] = __uint_as_float(f2tf(wv[i].x));
            Ws[wrow][wc0 + 4*i + 1] = __uint_as_float(f2tf(wv[i].y));
            Ws[wrow][wc0 + 4*i + 2] = __uint_as_float(f2tf(wv[i].z));
            Ws[wrow][wc0 + 4*i + 3] = __uint_as_float(f2tf(wv[i].w));
        }
        __syncthreads();

        // Prefetch next tile while computing this one
        if (k0 + 32 < C_DIM) {
            #pragma unroll
            for (int i = 0; i < 4; i++)
                xv[i] = *(const float4*)(X + (size_t)(m0 + xrow) * C_DIM + k0 + 32 + xc0 + 4 * i);
            #pragma unroll
            for (int i = 0; i < 2; i++)
                wv[i] = *(const float4*)(W + (size_t)(k0 + 32 + wrow) * D_HEAD + wc0 + 4 * i);
        }

        #pragma unroll
        for (int kc = 0; kc < 4; kc++) {
            uint32_t a0 = fb(Xs[w*16 + g    ][kc*8 + tig    ]);
            uint32_t a1 = fb(Xs[w*16 + g + 8][kc*8 + tig    ]);
            uint32_t a2 = fb(Xs[w*16 + g    ][kc*8 + tig + 4]);
            uint32_t a3 = fb(Xs[w*16 + g + 8][kc*8 + tig + 4]);
            #pragma unroll
            for (int nt = 0; nt < 8; nt++) {
                uint32_t b0 = fb(Ws[kc*8 + tig    ][nt*8 + g]);
                uint32_t b1 = fb(Ws[kc*8 + tig + 4][nt*8 + g]);
                mma_tf32(c[nt], a0, a1, a2, a3, b0, b1);
            }
        }
        __syncthreads();
    }

    // Epilogue: bias + store
    const int rlo = m0 + w*16 + g;
    const int rhi = rlo + 8;
    #pragma unroll
    for (int nt = 0; nt < 8; nt++) {
        int col = nt*8 + 2*tig;
        float b0 = bias[col], b1 = bias[col + 1];
        *(float2*)(out + (size_t)rlo * D_HEAD + col) = make_float2(c[nt][0] + b0, c[nt][1] + b1);
        *(float2*)(out + (size_t)rhi * D_HEAD + col) = make_float2(c[nt][2] + b0, c[nt][3] + b1);
    }
}

// ---------------------------------------------------------------------------
// Flash attention (tf32 MMA): CTA = (batch, 64-row q tile), 128 threads,
// 4 warps x 16 q-rows. Q fragments persistent in registers (scaled, tf32).
// K/V staged in smem stride-72 (conflict-free B-frag loads). Online softmax
// on C-fragments (2 quad shuffles per row reduction). P stored into the K
// smem region per-warp (tf32), PV via mma.
// ---------------------------------------------------------------------------
#define KS 72

__global__ __launch_bounds__(128, 4) void attn_kernel(float* __restrict__ out)
{
    __shared__ float k_s[64][KS];   // K tile [c][d]; reused as P [r][s]
    __shared__ float v_s[64][KS];   // V tile [s][d]

    const int b  = blockIdx.y;
    const int qi = (gridDim.x - 1) - blockIdx.x;   // long blocks first

    const int t    = threadIdx.x;
    const int lane = t & 31;
    const int w    = t >> 5;        // 0..3
    const int g    = lane >> 2;     // 0..7
    const int tig  = lane & 3;      // 0..3
    const int rlo  = w*16 + g;      // local q row
    const int rhi  = rlo + 8;

    const float* qp = g_q + ((size_t)b * T_LEN + qi * 64) * D_HEAD;
    const float* kb = g_k + (size_t)b * T_LEN * D_HEAD;
    const float* vb = g_v + (size_t)b * T_LEN * D_HEAD;

    // Q fragments (scale 1/sqrt(64) folded in)
    uint32_t qa[8][4];
    #pragma unroll
    for (int kc = 0; kc < 8; kc++) {
        qa[kc][0] = f2tf(0.125f * qp[rlo * D_HEAD + kc*8 + tig    ]);
        qa[kc][1] = f2tf(0.125f * qp[rhi * D_HEAD + kc*8 + tig    ]);
        qa[kc][2] = f2tf(0.125f * qp[rlo * D_HEAD + kc*8 + tig + 4]);
        qa[kc][3] = f2tf(0.125f * qp[rhi * D_HEAD + kc*8 + tig + 4]);
    }

    float oc[8][4] = {};
    float m_lo = -1e30f, m_hi = -1e30f, l_lo = 0.f, l_hi = 0.f;

    const int krow = t >> 1;          // 0..63
    const int kc0  = (t & 1) * 32;    // 0 or 32

    for (int j = 0; j <= qi; j++) {
        __syncthreads();   // prev iter's PV reads of k_s(P)/v_s complete

        // Load K,V tiles (cvt to tf32 at store)
        {
            const float* kp = kb + (size_t)(j*64 + krow) * D_HEAD + kc0;
            const float* vp = vb + (size_t)(j*64 + krow) * D_HEAD + kc0;
            #pragma unroll
            for (int i = 0; i < 8; i++) {
                float4 k4 = *(const float4*)(kp + 4*i);
                k_s[krow][kc0 + 4*i + 0] = __uint_as_float(f2tf(k4.x));
                k_s[krow][kc0 + 4*i + 1] = __uint_as_float(f2tf(k4.y));
                k_s[krow][kc0 + 4*i + 2] = __uint_as_float(f2tf(k4.z));
                k_s[krow][kc0 + 4*i + 3] = __uint_as_float(f2tf(k4.w));
                float4 v4 = *(const float4*)(vp + 4*i);
                v_s[krow][kc0 + 4*i + 0] = __uint_as_float(f2tf(v4.x));
                v_s[krow][kc0 + 4*i + 1] = __uint_as_float(f2tf(v4.y));
                v_s[krow][kc0 + 4*i + 2] = __uint_as_float(f2tf(v4.z));
                v_s[krow][kc0 + 4*i + 3] = __uint_as_float(f2tf(v4.w));
            }
        }
        __syncthreads();

        // S = Q @ K^T : warp computes rows [w*16, w*16+16) x all 64 cols
        float sc[8][4] = {};
        #pragma unroll
        for (int kc = 0; kc < 8; kc++) {
            #pragma unroll
            for (int nt = 0; nt < 8; nt++) {
                uint32_t b0 = fb(k_s[nt*8 + g][kc*8 + tig    ]);
                uint32_t b1 = fb(k_s[nt*8 + g][kc*8 + tig + 4]);
                mma_tf32(sc[nt], qa[kc][0], qa[kc][1], qa[kc][2], qa[kc][3], b0, b1);
            }
        }

        // Causal mask on the diagonal tile (local col vs local row)
        if (j == qi) {
            #pragma unroll
            for (int nt = 0; nt < 8; nt++) {
                int cb = nt*8 + 2*tig;
                if (cb     > rlo) sc[nt][0] = -1e30f;
                if (cb + 1 > rlo) sc[nt][1] = -1e30f;
                if (cb     > rhi) sc[nt][2] = -1e30f;
                if (cb + 1 > rhi) sc[nt][3] = -1e30f;
            }
        }

        // Online softmax: row reduction = 16 thread-local vals + 2 quad shuffles
        float mx0 = -1e30f, mx1 = -1e30f;
        #pragma unroll
        for (int nt = 0; nt < 8; nt++) {
            mx0 = fmaxf(mx0, fmaxf(sc[nt][0], sc[nt][1]));
            mx1 = fmaxf(mx1, fmaxf(sc[nt][2], sc[nt][3]));
        }
        mx0 = fmaxf(mx0, __shfl_xor_sync(0xffffffffu, mx0, 1));
        mx0 = fmaxf(mx0, __shfl_xor_sync(0xffffffffu, mx0, 2));
        mx1 = fmaxf(mx1, __shfl_xor_sync(0xffffffffu, mx1, 1));
        mx1 = fmaxf(mx1, __shfl_xor_sync(0xffffffffu, mx1, 2));

        float mn0 = fmaxf(m_lo, mx0);
        float mn1 = fmaxf(m_hi, mx1);
        float s0 = 0.f, s1 = 0.f;
        #pragma unroll
        for (int nt = 0; nt < 8; nt++) {
            sc[nt][0] = __expf(sc[nt][0] - mn0); s0 += sc[nt][0];
            sc[nt][1] = __expf(sc[nt][1] - mn0); s0 += sc[nt][1];
            sc[nt][2] = __expf(sc[nt][2] - mn1); s1 += sc[nt][2];
            sc[nt][3] = __expf(sc[nt][3] - mn1); s1 += sc[nt][3];
        }
        s0 += __shfl_xor_sync(0xffffffffu, s0, 1);
        s0 += __shfl_xor_sync(0xffffffffu, s0, 2);
        s1 += __shfl_xor_sync(0xffffffffu, s1, 1);
        s1 += __shfl_xor_sync(0xffffffffu, s1, 2);

        float a0 = __expf(m_lo - mn0);
        float a1 = __expf(m_hi - mn1);
        l_lo = l_lo * a0 + s0;  m_lo = mn0;
        l_hi = l_hi * a1 + s1;  m_hi = mn1;
        #pragma unroll
        for (int nt = 0; nt < 8; nt++) {
            oc[nt][0] *= a0; oc[nt][1] *= a0;
            oc[nt][2] *= a1; oc[nt][3] *= a1;
        }

        __syncthreads();   // all warps finished reading k_s (S GEMM)

        // Store P into k_s rows [w*16, w*16+16) — per-warp private strip
        {
            float* plo = &k_s[rlo][0];
            float* phi = &k_s[rhi][0];
            #pragma unroll
            for (int nt = 0; nt < 8; nt++) {
                int cb = nt*8 + 2*tig;
                *(float2*)&plo[cb] = make_float2(__uint_as_float(f2tf(sc[nt][0])),
                                                 __uint_as_float(f2tf(sc[nt][1])));
                *(float2*)&phi[cb] = make_float2(__uint_as_float(f2tf(sc[nt][2])),
                                                 __uint_as_float(f2tf(sc[nt][3])));
            }
        }
        __syncwarp();

        // O += P @ V
        #pragma unroll
        for (int kc = 0; kc < 8; kc++) {
            uint32_t pa0 = fb(k_s[rlo][kc*8 + tig    ]);
            uint32_t pa1 = fb(k_s[rhi][kc*8 + tig    ]);
            uint32_t pa2 = fb(k_s[rlo][kc*8 + tig + 4]);
            uint32_t pa3 = fb(k_s[rhi][kc*8 + tig + 4]);
            #pragma unroll
            for (int nt = 0; nt < 8; nt++) {
                uint32_t b0 = fb(v_s[kc*8 + tig    ][nt*8 + g]);
                uint32_t b1 = fb(v_s[kc*8 + tig + 4][nt*8 + g]);
                mma_tf32(oc[nt], pa0, pa1, pa2, pa3, b0, b1);
            }
        }
    }

    // Epilogue: normalize and store
    float i0 = 1.0f / l_lo;
    float i1 = 1.0f / l_hi;
    float* ob = out + ((size_t)b * T_LEN + qi * 64) * D_HEAD;
    #pragma unroll
    for (int nt = 0; nt < 8; nt++) {
        int col = nt*8 + 2*tig;
        *(float2*)(ob + (size_t)rlo * D_HEAD + col) = make_float2(oc[nt][0] * i0, oc[nt][1] * i0);
        *(float2*)(ob + (size_t)rhi * D_HEAD + col) = make_float2(oc[nt][2] * i1, oc[nt][3] * i1);
    }
}

// ---------------------------------------------------------------------------
extern "C" void kernel_launch(void* const* d_in, const int* in_sizes, int n_in,
                              void* d_out, int out_size)
{
    (void)in_sizes; (void)n_in; (void)out_size;
    const float* Q  = (const float*)d_in[0];
    const float* K  = (const float*)d_in[1];
    const float* V  = (const float*)d_in[2];
    const float* Wq = (const float*)d_in[3];
    const float* bq = (const float*)d_in[4];
    const float* Wk = (const float*)d_in[5];
    const float* bk = (const float*)d_in[6];
    const float* Wv = (const float*)d_in[7];
    const float* bv = (const float*)d_in[8];

    dim3 pg(M_ROWS / 128, 3);
    proj_kernel<<<pg, 256>>>(Q, K, V, Wq, bq, Wk, bk, Wv, bv);

    dim3 ag(T_LEN / 64, B_SZ);
    attn_kernel<<<ag, 128>>>((float*)d_out);
}

// round 5
// speedup vs baseline: 4.2194x; 1.3396x over previous
#include <cuda_runtime.h>
#include <stdint.h>
#include <math.h>

#define C_DIM  1024
#define D_HEAD 64
#define B_SZ   4
#define T_LEN  4096
#define M_ROWS (B_SZ * T_LEN)
#define NQT    (T_LEN / 64)      // 64 q-tiles per batch
#define CHUNK  16                // k-tiles per CTA (split-KV)
#define MAXCH  4                 // max chunks per q-tile

// Scratch for projected q, k, v
__device__ float g_q[M_ROWS * D_HEAD];
__device__ float g_k[M_ROWS * D_HEAD];
__device__ float g_v[M_ROWS * D_HEAD];

// Split-KV partials: [b][qi][ci] -> 64x64 O, 64 m, 64 l
__device__ float g_pO[B_SZ * NQT * MAXCH * 64 * 64];
__device__ float g_pm[B_SZ * NQT * MAXCH * 64];
__device__ float g_pl[B_SZ * NQT * MAXCH * 64];

__device__ __forceinline__ uint32_t f2tf(float x) {
    uint32_t r; asm("cvt.rna.tf32.f32 %0, %1;" : "=r"(r) : "f"(x)); return r;
}
__device__ __forceinline__ uint32_t fb(float x) { return __float_as_uint(x); }

__device__ __forceinline__ void mma_tf32(float c[4],
    uint32_t a0, uint32_t a1, uint32_t a2, uint32_t a3,
    uint32_t b0, uint32_t b1)
{
    asm volatile(
        "mma.sync.aligned.m16n8k8.row.col.f32.tf32.tf32.f32 "
        "{%0,%1,%2,%3}, {%4,%5,%6,%7}, {%8,%9}, {%0,%1,%2,%3};"
        : "+f"(c[0]), "+f"(c[1]), "+f"(c[2]), "+f"(c[3])
        : "r"(a0), "r"(a1), "r"(a2), "r"(a3), "r"(b0), "r"(b1));
}

// ---------------------------------------------------------------------------
// Projection GEMM (tf32 MMA) — unchanged from round 4.
// ---------------------------------------------------------------------------
#define XS_STRIDE 40
#define WS_STRIDE 72

__global__ __launch_bounds__(256) void proj_kernel(
    const float* __restrict__ Xq, const float* __restrict__ Xk, const float* __restrict__ Xv,
    const float* __restrict__ Wq, const float* __restrict__ bq,
    const float* __restrict__ Wk, const float* __restrict__ bk,
    const float* __restrict__ Wv, const float* __restrict__ bv)
{
    __shared__ float Xs[128][XS_STRIDE];
    __shared__ float Ws[32][WS_STRIDE];

    const float* X; const float* W; const float* bias; float* out;
    if (blockIdx.y == 0)      { X = Xq; W = Wq; bias = bq; out = g_q; }
    else if (blockIdx.y == 1) { X = Xk; W = Wk; bias = bk; out = g_k; }
    else                      { X = Xv; W = Wv; bias = bv; out = g_v; }

    const int t    = threadIdx.x;
    const int lane = t & 31;
    const int w    = t >> 5;
    const int g    = lane >> 2;
    const int tig  = lane & 3;
    const int m0   = blockIdx.x * 128;

    const int xrow = t >> 1;
    const int xc0  = (t & 1) * 16;
    const int wrow = t >> 3;
    const int wc0  = (t & 7) * 8;

    float4 xv[4], wv[2];
    #pragma unroll
    for (int i = 0; i < 4; i++)
        xv[i] = *(const float4*)(X + (size_t)(m0 + xrow) * C_DIM + xc0 + 4 * i);
    #pragma unroll
    for (int i = 0; i < 2; i++)
        wv[i] = *(const float4*)(W + (size_t)wrow * D_HEAD + wc0 + 4 * i);

    float c[8][4] = {};

    for (int k0 = 0; k0 < C_DIM; k0 += 32) {
        #pragma unroll
        for (int i = 0; i < 4; i++) {
            Xs[xrow][xc0 + 4*i + 0] = __uint_as_float(f2tf(xv[i].x));
            Xs[xrow][xc0 + 4*i + 1] = __uint_as_float(f2tf(xv[i].y));
            Xs[xrow][xc0 + 4*i + 2] = __uint_as_float(f2tf(xv[i].z));
            Xs[xrow][xc0 + 4*i + 3] = __uint_as_float(f2tf(xv[i].w));
        }
        #pragma unroll
        for (int i = 0; i < 2; i++) {
            Ws[wrow][wc0 + 4*i + 0] = __uint_as_float(f2tf(wv[i].x));
            Ws[wrow][wc0 + 4*i + 1] = __uint_as_float(f2tf(wv[i].y));
            Ws[wrow][wc0 + 4*i + 2] = __uint_as_float(f2tf(wv[i].z));
            Ws[wrow][wc0 + 4*i + 3] = __uint_as_float(f2tf(wv[i].w));
        }
        __syncthreads();

        if (k0 + 32 < C_DIM) {
            #pragma unroll
            for (int i = 0; i < 4; i++)
                xv[i] = *(const float4*)(X + (size_t)(m0 + xrow) * C_DIM + k0 + 32 + xc0 + 4 * i);
            #pragma unroll
            for (int i = 0; i < 2; i++)
                wv[i] = *(const float4*)(W + (size_t)(k0 + 32 + wrow) * D_HEAD + wc0 + 4 * i);
        }

        #pragma unroll
        for (int kc = 0; kc < 4; kc++) {
            uint32_t a0 = fb(Xs[w*16 + g    ][kc*8 + tig    ]);
            uint32_t a1 = fb(Xs[w*16 + g + 8][kc*8 + tig    ]);
            uint32_t a2 = fb(Xs[w*16 + g    ][kc*8 + tig + 4]);
            uint32_t a3 = fb(Xs[w*16 + g + 8][kc*8 + tig + 4]);
            #pragma unroll
            for (int nt = 0; nt < 8; nt++) {
                uint32_t b0 = fb(Ws[kc*8 + tig    ][nt*8 + g]);
                uint32_t b1 = fb(Ws[kc*8 + tig + 4][nt*8 + g]);
                mma_tf32(c[nt], a0, a1, a2, a3, b0, b1);
            }
        }
        __syncthreads();
    }

    const int rlo = m0 + w*16 + g;
    const int rhi = rlo + 8;
    #pragma unroll
    for (int nt = 0; nt < 8; nt++) {
        int col = nt*8 + 2*tig;
        float b0 = bias[col], b1 = bias[col + 1];
        *(float2*)(out + (size_t)rlo * D_HEAD + col) = make_float2(c[nt][0] + b0, c[nt][1] + b1);
        *(float2*)(out + (size_t)rhi * D_HEAD + col) = make_float2(c[nt][2] + b0, c[nt][3] + b1);
    }
}

// ---------------------------------------------------------------------------
// Flash attention partial (split-KV, tf32 MMA).
// CTA = (batch, q-tile qi, chunk ci); processes k-tiles [ci*16, min(ci*16+16, qi+1)).
// Writes unnormalized O + per-row (m, l) to scratch.
// Per batch: 160 CTAs (qi<16:1 chunk; <32:2; <48:3; <64:4).
// ---------------------------------------------------------------------------
#define KS 72

__global__ __launch_bounds__(128, 4) void attn_partial_kernel()
{
    __shared__ float k_s[64][KS];   // K tile [c][d]; reused as P [r][s]
    __shared__ float v_s[64][KS];   // V tile [s][d]

    const int b   = blockIdx.y;
    const int idx = 159 - blockIdx.x;     // heavy q-tiles first
    int qi, ci;
    if (idx < 16)      { qi = idx;                 ci = 0; }
    else if (idx < 48) { int e = idx - 16; qi = 16 + (e >> 1); ci = e & 1; }
    else if (idx < 96) { int e = idx - 48; qi = 32 + e / 3;    ci = e % 3; }
    else               { int e = idx - 96; qi = 48 + (e >> 2); ci = e & 3; }

    const int j0   = ci * CHUNK;
    const int jend = min(j0 + CHUNK, qi + 1);

    const int t    = threadIdx.x;
    const int lane = t & 31;
    const int w    = t >> 5;
    const int g    = lane >> 2;
    const int tig  = lane & 3;
    const int rlo  = w*16 + g;
    const int rhi  = rlo + 8;

    const float* qp = g_q + ((size_t)b * T_LEN + qi * 64) * D_HEAD;
    const float* kb = g_k + (size_t)b * T_LEN * D_HEAD;
    const float* vb = g_v + (size_t)b * T_LEN * D_HEAD;

    // Q fragments (scale folded in)
    uint32_t qa[8][4];
    #pragma unroll
    for (int kc = 0; kc < 8; kc++) {
        qa[kc][0] = f2tf(0.125f * qp[rlo * D_HEAD + kc*8 + tig    ]);
        qa[kc][1] = f2tf(0.125f * qp[rhi * D_HEAD + kc*8 + tig    ]);
        qa[kc][2] = f2tf(0.125f * qp[rlo * D_HEAD + kc*8 + tig + 4]);
        qa[kc][3] = f2tf(0.125f * qp[rhi * D_HEAD + kc*8 + tig + 4]);
    }

    float oc[8][4] = {};
    float m_lo = -1e30f, m_hi = -1e30f, l_lo = 0.f, l_hi = 0.f;

    const int krow = t >> 1;
    const int kc0  = (t & 1) * 32;

    for (int j = j0; j < jend; j++) {
        __syncthreads();

        {
            const float* kp = kb + (size_t)(j*64 + krow) * D_HEAD + kc0;
            const float* vp = vb + (size_t)(j*64 + krow) * D_HEAD + kc0;
            #pragma unroll
            for (int i = 0; i < 8; i++) {
                float4 k4 = *(const float4*)(kp + 4*i);
                k_s[krow][kc0 + 4*i + 0] = __uint_as_float(f2tf(k4.x));
                k_s[krow][kc0 + 4*i + 1] = __uint_as_float(f2tf(k4.y));
                k_s[krow][kc0 + 4*i + 2] = __uint_as_float(f2tf(k4.z));
                k_s[krow][kc0 + 4*i + 3] = __uint_as_float(f2tf(k4.w));
                float4 v4 = *(const float4*)(vp + 4*i);
                v_s[krow][kc0 + 4*i + 0] = __uint_as_float(f2tf(v4.x));
                v_s[krow][kc0 + 4*i + 1] = __uint_as_float(f2tf(v4.y));
                v_s[krow][kc0 + 4*i + 2] = __uint_as_float(f2tf(v4.z));
                v_s[krow][kc0 + 4*i + 3] = __uint_as_float(f2tf(v4.w));
            }
        }
        __syncthreads();

        // S = Q @ K^T
        float sc[8][4] = {};
        #pragma unroll
        for (int kc = 0; kc < 8; kc++) {
            #pragma unroll
            for (int nt = 0; nt < 8; nt++) {
                uint32_t b0 = fb(k_s[nt*8 + g][kc*8 + tig    ]);
                uint32_t b1 = fb(k_s[nt*8 + g][kc*8 + tig + 4]);
                mma_tf32(sc[nt], qa[kc][0], qa[kc][1], qa[kc][2], qa[kc][3], b0, b1);
            }
        }

        if (j == qi) {
            #pragma unroll
            for (int nt = 0; nt < 8; nt++) {
                int cb = nt*8 + 2*tig;
                if (cb     > rlo) sc[nt][0] = -1e30f;
                if (cb + 1 > rlo) sc[nt][1] = -1e30f;
                if (cb     > rhi) sc[nt][2] = -1e30f;
                if (cb + 1 > rhi) sc[nt][3] = -1e30f;
            }
        }

        // Online softmax
        float mx0 = -1e30f, mx1 = -1e30f;
        #pragma unroll
        for (int nt = 0; nt < 8; nt++) {
            mx0 = fmaxf(mx0, fmaxf(sc[nt][0], sc[nt][1]));
            mx1 = fmaxf(mx1, fmaxf(sc[nt][2], sc[nt][3]));
        }
        mx0 = fmaxf(mx0, __shfl_xor_sync(0xffffffffu, mx0, 1));
        mx0 = fmaxf(mx0, __shfl_xor_sync(0xffffffffu, mx0, 2));
        mx1 = fmaxf(mx1, __shfl_xor_sync(0xffffffffu, mx1, 1));
        mx1 = fmaxf(mx1, __shfl_xor_sync(0xffffffffu, mx1, 2));

        float mn0 = fmaxf(m_lo, mx0);
        float mn1 = fmaxf(m_hi, mx1);
        float s0 = 0.f, s1 = 0.f;
        #pragma unroll
        for (int nt = 0; nt < 8; nt++) {
            sc[nt][0] = __expf(sc[nt][0] - mn0); s0 += sc[nt][0];
            sc[nt][1] = __expf(sc[nt][1] - mn0); s0 += sc[nt][1];
            sc[nt][2] = __expf(sc[nt][2] - mn1); s1 += sc[nt][2];
            sc[nt][3] = __expf(sc[nt][3] - mn1); s1 += sc[nt][3];
        }
        s0 += __shfl_xor_sync(0xffffffffu, s0, 1);
        s0 += __shfl_xor_sync(0xffffffffu, s0, 2);
        s1 += __shfl_xor_sync(0xffffffffu, s1, 1);
        s1 += __shfl_xor_sync(0xffffffffu, s1, 2);

        float a0 = __expf(m_lo - mn0);
        float a1 = __expf(m_hi - mn1);
        l_lo = l_lo * a0 + s0;  m_lo = mn0;
        l_hi = l_hi * a1 + s1;  m_hi = mn1;
        #pragma unroll
        for (int nt = 0; nt < 8; nt++) {
            oc[nt][0] *= a0; oc[nt][1] *= a0;
            oc[nt][2] *= a1; oc[nt][3] *= a1;
        }

        __syncthreads();

        // P -> k_s (per-warp strip)
        {
            float* plo = &k_s[rlo][0];
            float* phi = &k_s[rhi][0];
            #pragma unroll
            for (int nt = 0; nt < 8; nt++) {
                int cb = nt*8 + 2*tig;
                *(float2*)&plo[cb] = make_float2(__uint_as_float(f2tf(sc[nt][0])),
                                                 __uint_as_float(f2tf(sc[nt][1])));
                *(float2*)&phi[cb] = make_float2(__uint_as_float(f2tf(sc[nt][2])),
                                                 __uint_as_float(f2tf(sc[nt][3])));
            }
        }
        __syncwarp();

        // O += P @ V
        #pragma unroll
        for (int kc = 0; kc < 8; kc++) {
            uint32_t pa0 = fb(k_s[rlo][kc*8 + tig    ]);
            uint32_t pa1 = fb(k_s[rhi][kc*8 + tig    ]);
            uint32_t pa2 = fb(k_s[rlo][kc*8 + tig + 4]);
            uint32_t pa3 = fb(k_s[rhi][kc*8 + tig + 4]);
            #pragma unroll
            for (int nt = 0; nt < 8; nt++) {
                uint32_t b0 = fb(v_s[kc*8 + tig    ][nt*8 + g]);
                uint32_t b1 = fb(v_s[kc*8 + tig + 4][nt*8 + g]);
                mma_tf32(oc[nt], pa0, pa1, pa2, pa3, b0, b1);
            }
        }
    }

    // Write partial (unnormalized) + m/l
    const size_t pbase = ((size_t)(b * NQT + qi) * MAXCH + ci);
    float* pO = g_pO + pbase * 64 * 64;
    #pragma unroll
    for (int nt = 0; nt < 8; nt++) {
        int col = nt*8 + 2*tig;
        *(float2*)(pO + rlo * 64 + col) = make_float2(oc[nt][0], oc[nt][1]);
        *(float2*)(pO + rhi * 64 + col) = make_float2(oc[nt][2], oc[nt][3]);
    }
    if (tig == 0) {
        g_pm[pbase * 64 + rlo] = m_lo;
        g_pm[pbase * 64 + rhi] = m_hi;
        g_pl[pbase * 64 + rlo] = l_lo;
        g_pl[pbase * 64 + rhi] = l_hi;
    }
}

// ---------------------------------------------------------------------------
// Merge: combine up to 4 partials per q-tile row (log-sum-exp), normalize.
// Grid (NQT, B_SZ), block 256: thread -> (row = t>>2, 16 cols).
// ---------------------------------------------------------------------------
__global__ __launch_bounds__(256) void attn_merge_kernel(float* __restrict__ out)
{
    const int qi = blockIdx.x;
    const int b  = blockIdx.y;
    const int nc = qi / CHUNK + 1;

    const int t   = threadIdx.x;
    const int row = t >> 2;
    const int c0  = (t & 3) * 16;

    const size_t pbase = (size_t)(b * NQT + qi) * MAXCH;

    float mv[MAXCH], lv[MAXCH];
    float M = -1e30f;
    for (int ci = 0; ci < nc; ci++) {
        mv[ci] = g_pm[(pbase + ci) * 64 + row];
        lv[ci] = g_pl[(pbase + ci) * 64 + row];
        M = fmaxf(M, mv[ci]);
    }
    float L = 0.f;
    for (int ci = 0; ci < nc; ci++) L += lv[ci] * __expf(mv[ci] - M);

    float acc[16] = {};
    for (int ci = 0; ci < nc; ci++) {
        float wgt = __expf(mv[ci] - M);
        const float* pO = g_pO + (pbase + ci) * 64 * 64 + row * 64 + c0;
        #pragma unroll
        for (int u = 0; u < 4; u++) {
            float4 v4 = *(const float4*)(pO + 4*u);
            acc[4*u + 0] += wgt * v4.x;
            acc[4*u + 1] += wgt * v4.y;
            acc[4*u + 2] += wgt * v4.z;
            acc[4*u + 3] += wgt * v4.w;
        }
    }
    float inv = 1.0f / L;
    float* ob = out + ((size_t)b * T_LEN + qi * 64 + row) * D_HEAD + c0;
    #pragma unroll
    for (int u = 0; u < 4; u++)
        *(float4*)(ob + 4*u) = make_float4(acc[4*u + 0] * inv, acc[4*u + 1] * inv,
                                           acc[4*u + 2] * inv, acc[4*u + 3] * inv);
}

// ---------------------------------------------------------------------------
extern "C" void kernel_launch(void* const* d_in, const int* in_sizes, int n_in,
                              void* d_out, int out_size)
{
    (void)in_sizes; (void)n_in; (void)out_size;
    const float* Q  = (const float*)d_in[0];
    const float* K  = (const float*)d_in[1];
    const float* V  = (const float*)d_in[2];
    const float* Wq = (const float*)d_in[3];
    const float* bq = (const float*)d_in[4];
    const float* Wk = (const float*)d_in[5];
    const float* bk = (const float*)d_in[6];
    const float* Wv = (const float*)d_in[7];
    const float* bv = (const float*)d_in[8];

    dim3 pg(M_ROWS / 128, 3);
    proj_kernel<<<pg, 256>>>(Q, K, V, Wq, bq, Wk, bk, Wv, bv);

    dim3 ag(160, B_SZ);
    attn_partial_kernel<<<ag, 128>>>();

    dim3 mg(NQT, B_SZ);
    attn_merge_kernel<<<mg, 256>>>((float*)d_out);
}

// round 6
// speedup vs baseline: 4.8061x; 1.1390x over previous
#include <cuda_runtime.h>
#include <stdint.h>

#define C_DIM  1024
#define D_HEAD 64
#define B_SZ   4
#define T_LEN  4096
#define M_ROWS (B_SZ * T_LEN)
#define NQT    (T_LEN / 64)
#define CHUNK  8
#define MAXCH  8
#define NCTA_B 288            // sum_{m=0..7} 8*(m+1)

// Projected q (pre-scaled by 0.125, tf32 bits), k, v (tf32 bits)
__device__ float g_q[M_ROWS * D_HEAD];
__device__ float g_k[M_ROWS * D_HEAD];
__device__ float g_v[M_ROWS * D_HEAD];

// Split-KV partials
__device__ float g_pO[B_SZ * NQT * MAXCH * 64 * 64];
__device__ float g_pm[B_SZ * NQT * MAXCH * 64];
__device__ float g_pl[B_SZ * NQT * MAXCH * 64];

__device__ __forceinline__ uint32_t f2tf(float x) {
    uint32_t r; asm("cvt.rna.tf32.f32 %0, %1;" : "=r"(r) : "f"(x)); return r;
}
__device__ __forceinline__ uint32_t fb(float x) { return __float_as_uint(x); }

__device__ __forceinline__ void mma_tf32(float c[4],
    uint32_t a0, uint32_t a1, uint32_t a2, uint32_t a3,
    uint32_t b0, uint32_t b1)
{
    asm volatile(
        "mma.sync.aligned.m16n8k8.row.col.f32.tf32.tf32.f32 "
        "{%0,%1,%2,%3}, {%4,%5,%6,%7}, {%8,%9}, {%0,%1,%2,%3};"
        : "+f"(c[0]), "+f"(c[1]), "+f"(c[2]), "+f"(c[3])
        : "r"(a0), "r"(a1), "r"(a2), "r"(a3), "r"(b0), "r"(b1));
}

__device__ __forceinline__ void cp16(float* dst_smem, const float* src) {
    uint32_t d = (uint32_t)__cvta_generic_to_shared(dst_smem);
    asm volatile("cp.async.ca.shared.global [%0], [%1], 16;" :: "r"(d), "l"(src) : "memory");
}
#define CP_COMMIT() asm volatile("cp.async.commit_group;" ::: "memory")
#define CP_WAIT(N)  asm volatile("cp.async.wait_group %0;" :: "n"(N) : "memory")

// ---------------------------------------------------------------------------
// Projection GEMM (tf32 MMA). Epilogue stores tf32 bits (q pre-scaled 0.125).
// ---------------------------------------------------------------------------
#define XS_STRIDE 36
#define WS_STRIDE 72

__global__ __launch_bounds__(256) void proj_kernel(
    const float* __restrict__ Xq, const float* __restrict__ Xk, const float* __restrict__ Xv,
    const float* __restrict__ Wq, const float* __restrict__ bq,
    const float* __restrict__ Wk, const float* __restrict__ bk,
    const float* __restrict__ Wv, const float* __restrict__ bv)
{
    __shared__ float Xs[128][XS_STRIDE];
    __shared__ float Ws[32][WS_STRIDE];

    const float* X; const float* W; const float* bias; float* out; float osc;
    if (blockIdx.y == 0)      { X = Xq; W = Wq; bias = bq; out = g_q; osc = 0.125f; }
    else if (blockIdx.y == 1) { X = Xk; W = Wk; bias = bk; out = g_k; osc = 1.0f; }
    else                      { X = Xv; W = Wv; bias = bv; out = g_v; osc = 1.0f; }

    const int t    = threadIdx.x;
    const int lane = t & 31;
    const int w    = t >> 5;
    const int g    = lane >> 2;
    const int tig  = lane & 3;
    const int m0   = blockIdx.x * 128;

    const int xrow = t >> 1;
    const int xc0  = (t & 1) * 16;
    const int wrow = t >> 3;
    const int wc0  = (t & 7) * 8;

    float4 xv[4], wv[2];
    #pragma unroll
    for (int i = 0; i < 4; i++)
        xv[i] = *(const float4*)(X + (size_t)(m0 + xrow) * C_DIM + xc0 + 4 * i);
    #pragma unroll
    for (int i = 0; i < 2; i++)
        wv[i] = *(const float4*)(W + (size_t)wrow * D_HEAD + wc0 + 4 * i);

    float c[8][4] = {};

    for (int k0 = 0; k0 < C_DIM; k0 += 32) {
        #pragma unroll
        for (int i = 0; i < 4; i++) {
            Xs[xrow][xc0 + 4*i + 0] = __uint_as_float(f2tf(xv[i].x));
            Xs[xrow][xc0 + 4*i + 1] = __uint_as_float(f2tf(xv[i].y));
            Xs[xrow][xc0 + 4*i + 2] = __uint_as_float(f2tf(xv[i].z));
            Xs[xrow][xc0 + 4*i + 3] = __uint_as_float(f2tf(xv[i].w));
        }
        #pragma unroll
        for (int i = 0; i < 2; i++) {
            Ws[wrow][wc0 + 4*i + 0] = __uint_as_float(f2tf(wv[i].x));
            Ws[wrow][wc0 + 4*i + 1] = __uint_as_float(f2tf(wv[i].y));
            Ws[wrow][wc0 + 4*i + 2] = __uint_as_float(f2tf(wv[i].z));
            Ws[wrow][wc0 + 4*i + 3] = __uint_as_float(f2tf(wv[i].w));
        }
        __syncthreads();

        if (k0 + 32 < C_DIM) {
            #pragma unroll
            for (int i = 0; i < 4; i++)
                xv[i] = *(const float4*)(X + (size_t)(m0 + xrow) * C_DIM + k0 + 32 + xc0 + 4 * i);
            #pragma unroll
            for (int i = 0; i < 2; i++)
                wv[i] = *(const float4*)(W + (size_t)(k0 + 32 + wrow) * D_HEAD + wc0 + 4 * i);
        }

        #pragma unroll
        for (int kc = 0; kc < 4; kc++) {
            uint32_t a0 = fb(Xs[w*16 + g    ][kc*8 + tig    ]);
            uint32_t a1 = fb(Xs[w*16 + g + 8][kc*8 + tig    ]);
            uint32_t a2 = fb(Xs[w*16 + g    ][kc*8 + tig + 4]);
            uint32_t a3 = fb(Xs[w*16 + g + 8][kc*8 + tig + 4]);
            #pragma unroll
            for (int nt = 0; nt < 8; nt++) {
                uint32_t b0 = fb(Ws[kc*8 + tig    ][nt*8 + g]);
                uint32_t b1 = fb(Ws[kc*8 + tig + 4][nt*8 + g]);
                mma_tf32(c[nt], a0, a1, a2, a3, b0, b1);
            }
        }
        __syncthreads();
    }

    const int rlo = m0 + w*16 + g;
    const int rhi = rlo + 8;
    #pragma unroll
    for (int nt = 0; nt < 8; nt++) {
        int col = nt*8 + 2*tig;
        float b0 = bias[col], b1 = bias[col + 1];
        *(float2*)(out + (size_t)rlo * D_HEAD + col) =
            make_float2(__uint_as_float(f2tf((c[nt][0] + b0) * osc)),
                        __uint_as_float(f2tf((c[nt][1] + b1) * osc)));
        *(float2*)(out + (size_t)rhi * D_HEAD + col) =
            make_float2(__uint_as_float(f2tf((c[nt][2] + b0) * osc)),
                        __uint_as_float(f2tf((c[nt][3] + b1) * osc)));
    }
}

// ---------------------------------------------------------------------------
// Flash attention partial (split-KV, tf32 MMA, cp.async pipeline).
// K double-buffered (stride 68), V single-buffered (stride 72), P -> current
// K buffer. Per batch 288 CTAs of <=8 k-tiles.
// ---------------------------------------------------------------------------
#define KST 68
#define VST 72
#define SMEM_ATTN ((2*64*KST + 64*VST) * 4)

__global__ __launch_bounds__(128, 4) void attn_partial_kernel()
{
    extern __shared__ float sm[];
    float* ksA = sm;                    // [64][KST]
    float* ksB = sm + 64*KST;           // [64][KST]
    float* vs  = sm + 2*64*KST;         // [64][VST]

    const int b   = blockIdx.y;
    int idx = NCTA_B - 1 - blockIdx.x;  // heavy chunks first
    int m = 0, base = 0;
    while (idx >= base + 8*(m+1)) { base += 8*(m+1); ++m; }
    int r  = idx - base;
    int qi = 8*m + r / (m+1);
    int ci = r % (m+1);
    const int j0   = ci * CHUNK;
    const int jend = min(j0 + CHUNK, qi + 1);

    const int t    = threadIdx.x;
    const int lane = t & 31;
    const int w    = t >> 5;
    const int g    = lane >> 2;
    const int tig  = lane & 3;
    const int rlo  = w*16 + g;
    const int rhi  = rlo + 8;

    const float* qp = g_q + ((size_t)b * T_LEN + qi * 64) * D_HEAD;
    const float* kb = g_k + (size_t)b * T_LEN * D_HEAD;
    const float* vb = g_v + (size_t)b * T_LEN * D_HEAD;

    const int row = t >> 1;           // 0..63
    const int c0  = (t & 1) * 32;     // 0 or 32

    // Prologue: async-load K tile j0 into ksA
    {
        const float* kp = kb + (size_t)(j0*64 + row) * D_HEAD + c0;
        #pragma unroll
        for (int i = 0; i < 8; i++)
            cp16(ksA + row*KST + c0 + 4*i, kp + 4*i);
        CP_COMMIT();
    }

    // Q fragments: already tf32 bits, pre-scaled
    uint32_t qa[8][4];
    #pragma unroll
    for (int kc = 0; kc < 8; kc++) {
        qa[kc][0] = fb(qp[rlo * D_HEAD + kc*8 + tig    ]);
        qa[kc][1] = fb(qp[rhi * D_HEAD + kc*8 + tig    ]);
        qa[kc][2] = fb(qp[rlo * D_HEAD + kc*8 + tig + 4]);
        qa[kc][3] = fb(qp[rhi * D_HEAD + kc*8 + tig + 4]);
    }

    float oc[8][4] = {};
    float m_lo = -1e30f, m_hi = -1e30f, l_lo = 0.f, l_hi = 0.f;

    for (int j = j0; j < jend; j++) {
        float* kcur = ((j - j0) & 1) ? ksB : ksA;
        float* knxt = ((j - j0) & 1) ? ksA : ksB;

        __syncthreads();   // (a) all warps done with prev iter (vs, knxt free)

        // V_j -> vs
        {
            const float* vp = vb + (size_t)(j*64 + row) * D_HEAD + c0;
            #pragma unroll
            for (int i = 0; i < 8; i++)
                cp16(vs + row*VST + c0 + 4*i, vp + 4*i);
            CP_COMMIT();
        }
        const bool kn = (j + 1 < jend);
        if (kn) {
            const float* kp = kb + (size_t)((j+1)*64 + row) * D_HEAD + c0;
            #pragma unroll
            for (int i = 0; i < 8; i++)
                cp16(knxt + row*KST + c0 + 4*i, kp + 4*i);
            CP_COMMIT();
        }

        if (kn) { CP_WAIT(2); } else { CP_WAIT(1); }   // K_j retired
        __syncthreads();   // (e) K_j visible to all

        // S = Q @ K^T
        float sc[8][4] = {};
        #pragma unroll
        for (int kc = 0; kc < 8; kc++) {
            #pragma unroll
            for (int nt = 0; nt < 8; nt++) {
                uint32_t b0 = fb(kcur[(nt*8 + g)*KST + kc*8 + tig    ]);
                uint32_t b1 = fb(kcur[(nt*8 + g)*KST + kc*8 + tig + 4]);
                mma_tf32(sc[nt], qa[kc][0], qa[kc][1], qa[kc][2], qa[kc][3], b0, b1);
            }
        }

        if (j == qi) {
            #pragma unroll
            for (int nt = 0; nt < 8; nt++) {
                int cb = nt*8 + 2*tig;
                if (cb     > rlo) sc[nt][0] = -1e30f;
                if (cb + 1 > rlo) sc[nt][1] = -1e30f;
                if (cb     > rhi) sc[nt][2] = -1e30f;
                if (cb + 1 > rhi) sc[nt][3] = -1e30f;
            }
        }

        // Online softmax
        float mx0 = -1e30f, mx1 = -1e30f;
        #pragma unroll
        for (int nt = 0; nt < 8; nt++) {
            mx0 = fmaxf(mx0, fmaxf(sc[nt][0], sc[nt][1]));
            mx1 = fmaxf(mx1, fmaxf(sc[nt][2], sc[nt][3]));
        }
        mx0 = fmaxf(mx0, __shfl_xor_sync(0xffffffffu, mx0, 1));
        mx0 = fmaxf(mx0, __shfl_xor_sync(0xffffffffu, mx0, 2));
        mx1 = fmaxf(mx1, __shfl_xor_sync(0xffffffffu, mx1, 1));
        mx1 = fmaxf(mx1, __shfl_xor_sync(0xffffffffu, mx1, 2));

        float mn0 = fmaxf(m_lo, mx0);
        float mn1 = fmaxf(m_hi, mx1);
        float s0 = 0.f, s1 = 0.f;
        #pragma unroll
        for (int nt = 0; nt < 8; nt++) {
            sc[nt][0] = __expf(sc[nt][0] - mn0); s0 += sc[nt][0];
            sc[nt][1] = __expf(sc[nt][1] - mn0); s0 += sc[nt][1];
            sc[nt][2] = __expf(sc[nt][2] - mn1); s1 += sc[nt][2];
            sc[nt][3] = __expf(sc[nt][3] - mn1); s1 += sc[nt][3];
        }
        s0 += __shfl_xor_sync(0xffffffffu, s0, 1);
        s0 += __shfl_xor_sync(0xffffffffu, s0, 2);
        s1 += __shfl_xor_sync(0xffffffffu, s1, 1);
        s1 += __shfl_xor_sync(0xffffffffu, s1, 2);

        float a0 = __expf(m_lo - mn0);
        float a1 = __expf(m_hi - mn1);
        l_lo = l_lo * a0 + s0;  m_lo = mn0;
        l_hi = l_hi * a1 + s1;  m_hi = mn1;
        #pragma unroll
        for (int nt = 0; nt < 8; nt++) {
            oc[nt][0] *= a0; oc[nt][1] *= a0;
            oc[nt][2] *= a1; oc[nt][3] *= a1;
        }

        if (kn) { CP_WAIT(1); } else { CP_WAIT(0); }   // V_j retired
        __syncthreads();   // (h) V visible; all warps done reading kcur (S)

        // P -> kcur rows [w*16, w*16+16)
        {
            float* plo = kcur + rlo*KST;
            float* phi = kcur + rhi*KST;
            #pragma unroll
            for (int nt = 0; nt < 8; nt++) {
                int cb = nt*8 + 2*tig;
                *(float2*)&plo[cb] = make_float2(__uint_as_float(f2tf(sc[nt][0])),
                                                 __uint_as_float(f2tf(sc[nt][1])));
                *(float2*)&phi[cb] = make_float2(__uint_as_float(f2tf(sc[nt][2])),
                                                 __uint_as_float(f2tf(sc[nt][3])));
            }
        }
        __syncwarp();

        // O += P @ V
        #pragma unroll
        for (int kc = 0; kc < 8; kc++) {
            uint32_t pa0 = fb(kcur[rlo*KST + kc*8 + tig    ]);
            uint32_t pa1 = fb(kcur[rhi*KST + kc*8 + tig    ]);
            uint32_t pa2 = fb(kcur[rlo*KST + kc*8 + tig + 4]);
            uint32_t pa3 = fb(kcur[rhi*KST + kc*8 + tig + 4]);
            #pragma unroll
            for (int nt = 0; nt < 8; nt++) {
                uint32_t b0 = fb(vs[(kc*8 + tig    )*VST + nt*8 + g]);
                uint32_t b1 = fb(vs[(kc*8 + tig + 4)*VST + nt*8 + g]);
                mma_tf32(oc[nt], pa0, pa1, pa2, pa3, b0, b1);
            }
        }
    }

    // Write partial (unnormalized) + m/l
    const size_t pbase = ((size_t)(b * NQT + qi) * MAXCH + ci);
    float* pO = g_pO + pbase * 64 * 64;
    #pragma unroll
    for (int nt = 0; nt < 8; nt++) {
        int col = nt*8 + 2*tig;
        *(float2*)(pO + rlo * 64 + col) = make_float2(oc[nt][0], oc[nt][1]);
        *(float2*)(pO + rhi * 64 + col) = make_float2(oc[nt][2], oc[nt][3]);
    }
    if (tig == 0) {
        g_pm[pbase * 64 + rlo] = m_lo;
        g_pm[pbase * 64 + rhi] = m_hi;
        g_pl[pbase * 64 + rlo] = l_lo;
        g_pl[pbase * 64 + rhi] = l_hi;
    }
}

// ---------------------------------------------------------------------------
// Merge: combine up to 8 partials per q-tile row (log-sum-exp), normalize.
// ---------------------------------------------------------------------------
__global__ __launch_bounds__(256) void attn_merge_kernel(float* __restrict__ out)
{
    const int qi = blockIdx.x;
    const int b  = blockIdx.y;
    const int nc = qi / CHUNK + 1;

    const int t   = threadIdx.x;
    const int row = t >> 2;
    const int c0  = (t & 3) * 16;

    const size_t pbase = (size_t)(b * NQT + qi) * MAXCH;

    float mv[MAXCH], lv[MAXCH];
    float M = -1e30f;
    for (int ci = 0; ci < nc; ci++) {
        mv[ci] = g_pm[(pbase + ci) * 64 + row];
        lv[ci] = g_pl[(pbase + ci) * 64 + row];
        M = fmaxf(M, mv[ci]);
    }
    float L = 0.f;
    for (int ci = 0; ci < nc; ci++) L += lv[ci] * __expf(mv[ci] - M);

    float acc[16] = {};
    for (int ci = 0; ci < nc; ci++) {
        float wgt = __expf(mv[ci] - M);
        const float* pO = g_pO + (pbase + ci) * 64 * 64 + row * 64 + c0;
        #pragma unroll
        for (int u = 0; u < 4; u++) {
            float4 v4 = *(const float4*)(pO + 4*u);
            acc[4*u + 0] += wgt * v4.x;
            acc[4*u + 1] += wgt * v4.y;
            acc[4*u + 2] += wgt * v4.z;
            acc[4*u + 3] += wgt * v4.w;
        }
    }
    float inv = 1.0f / L;
    float* ob = out + ((size_t)b * T_LEN + qi * 64 + row) * D_HEAD + c0;
    #pragma unroll
    for (int u = 0; u < 4; u++)
        *(float4*)(ob + 4*u) = make_float4(acc[4*u + 0] * inv, acc[4*u + 1] * inv,
                                           acc[4*u + 2] * inv, acc[4*u + 3] * inv);
}

// ---------------------------------------------------------------------------
extern "C" void kernel_launch(void* const* d_in, const int* in_sizes, int n_in,
                              void* d_out, int out_size)
{
    (void)in_sizes; (void)n_in; (void)out_size;
    const float* Q  = (const float*)d_in[0];
    const float* K  = (const float*)d_in[1];
    const float* V  = (const float*)d_in[2];
    const float* Wq = (const float*)d_in[3];
    const float* bq = (const float*)d_in[4];
    const float* Wk = (const float*)d_in[5];
    const float* bk = (const float*)d_in[6];
    const float* Wv = (const float*)d_in[7];
    const float* bv = (const float*)d_in[8];

    static bool attr_set = false;
    if (!attr_set) {
        cudaFuncSetAttribute(attn_partial_kernel,
                             cudaFuncAttributeMaxDynamicSharedMemorySize, SMEM_ATTN);
        attr_set = true;
    }

    dim3 pg(M_ROWS / 128, 3);
    proj_kernel<<<pg, 256>>>(Q, K, V, Wq, bq, Wk, bk, Wv, bv);

    dim3 ag(NCTA_B, B_SZ);
    attn_partial_kernel<<<ag, 128, SMEM_ATTN>>>();

    dim3 mg(NQT, B_SZ);
    attn_merge_kernel<<<mg, 256>>>((float*)d_out);
}

// round 7
// speedup vs baseline: 4.8995x; 1.0194x over previous
#include <cuda_runtime.h>
#include <stdint.h>

#define C_DIM  1024
#define D_HEAD 64
#define B_SZ   4
#define T_LEN  4096
#define M_ROWS (B_SZ * T_LEN)
#define NQT    (T_LEN / 128)     // 32 q-tiles (128 rows) per batch
#define CHUNK  8                 // k-tiles (64 wide) per CTA
#define MAXCH  8
#define NCTA_B 144               // sum_{qt=0..31} (qt/4 + 1)

// Projected q (pre-scaled 0.125, tf32 bits), k, v (tf32 bits)
__device__ float g_q[M_ROWS * D_HEAD];
__device__ float g_k[M_ROWS * D_HEAD];
__device__ float g_v[M_ROWS * D_HEAD];

// Split-KV partials: per (b, qt, ci): 128x64 O + 128 m + 128 l
__device__ float g_pO[B_SZ * NQT * MAXCH * 128 * 64];
__device__ float g_pm[B_SZ * NQT * MAXCH * 128];
__device__ float g_pl[B_SZ * NQT * MAXCH * 128];

__device__ __forceinline__ uint32_t f2tf(float x) {
    uint32_t r; asm("cvt.rna.tf32.f32 %0, %1;" : "=r"(r) : "f"(x)); return r;
}
__device__ __forceinline__ uint32_t fb(float x) { return __float_as_uint(x); }

__device__ __forceinline__ void mma_tf32(float c[4],
    uint32_t a0, uint32_t a1, uint32_t a2, uint32_t a3,
    uint32_t b0, uint32_t b1)
{
    asm volatile(
        "mma.sync.aligned.m16n8k8.row.col.f32.tf32.tf32.f32 "
        "{%0,%1,%2,%3}, {%4,%5,%6,%7}, {%8,%9}, {%0,%1,%2,%3};"
        : "+f"(c[0]), "+f"(c[1]), "+f"(c[2]), "+f"(c[3])
        : "r"(a0), "r"(a1), "r"(a2), "r"(a3), "r"(b0), "r"(b1));
}

__device__ __forceinline__ void cp16(float* dst_smem, const float* src) {
    uint32_t d = (uint32_t)__cvta_generic_to_shared(dst_smem);
    asm volatile("cp.async.ca.shared.global [%0], [%1], 16;" :: "r"(d), "l"(src) : "memory");
}
#define CP_COMMIT() asm volatile("cp.async.commit_group;" ::: "memory")
#define CP_WAIT(N)  asm volatile("cp.async.wait_group %0;" :: "n"(N) : "memory")

// ---------------------------------------------------------------------------
// Projection GEMM (tf32 MMA): 64-row CTAs, 128 threads, 4 warps x (16x64).
// Grid (256, 3) = 768 CTAs -> ~5 CTAs/SM for latency hiding.
// ---------------------------------------------------------------------------
#define XS_STRIDE 36
#define WS_STRIDE 72

__global__ __launch_bounds__(128) void proj_kernel(
    const float* __restrict__ Xq, const float* __restrict__ Xk, const float* __restrict__ Xv,
    const float* __restrict__ Wq, const float* __restrict__ bq,
    const float* __restrict__ Wk, const float* __restrict__ bk,
    const float* __restrict__ Wv, const float* __restrict__ bv)
{
    __shared__ float Xs[64][XS_STRIDE];
    __shared__ float Ws[32][WS_STRIDE];

    const float* X; const float* W; const float* bias; float* out; float osc;
    if (blockIdx.y == 0)      { X = Xq; W = Wq; bias = bq; out = g_q; osc = 0.125f; }
    else if (blockIdx.y == 1) { X = Xk; W = Wk; bias = bk; out = g_k; osc = 1.0f; }
    else                      { X = Xv; W = Wv; bias = bv; out = g_v; osc = 1.0f; }

    const int t    = threadIdx.x;
    const int lane = t & 31;
    const int w    = t >> 5;          // 0..3
    const int g    = lane >> 2;
    const int tig  = lane & 3;
    const int m0   = blockIdx.x * 64;

    const int xrow = t >> 1;          // 0..63
    const int xc0  = (t & 1) * 16;    // 0 or 16
    const int wrow = t >> 2;          // 0..31
    const int wc0  = (t & 3) * 16;    // 0,16,32,48

    float4 xv[4], wv[4];
    #pragma unroll
    for (int i = 0; i < 4; i++)
        xv[i] = *(const float4*)(X + (size_t)(m0 + xrow) * C_DIM + xc0 + 4 * i);
    #pragma unroll
    for (int i = 0; i < 4; i++)
        wv[i] = *(const float4*)(W + (size_t)wrow * D_HEAD + wc0 + 4 * i);

    float c[8][4] = {};

    for (int k0 = 0; k0 < C_DIM; k0 += 32) {
        #pragma unroll
        for (int i = 0; i < 4; i++) {
            Xs[xrow][xc0 + 4*i + 0] = __uint_as_float(f2tf(xv[i].x));
            Xs[xrow][xc0 + 4*i + 1] = __uint_as_float(f2tf(xv[i].y));
            Xs[xrow][xc0 + 4*i + 2] = __uint_as_float(f2tf(xv[i].z));
            Xs[xrow][xc0 + 4*i + 3] = __uint_as_float(f2tf(xv[i].w));
        }
        #pragma unroll
        for (int i = 0; i < 4; i++) {
            Ws[wrow][wc0 + 4*i + 0] = __uint_as_float(f2tf(wv[i].x));
            Ws[wrow][wc0 + 4*i + 1] = __uint_as_float(f2tf(wv[i].y));
            Ws[wrow][wc0 + 4*i + 2] = __uint_as_float(f2tf(wv[i].z));
            Ws[wrow][wc0 + 4*i + 3] = __uint_as_float(f2tf(wv[i].w));
        }
        __syncthreads();

        if (k0 + 32 < C_DIM) {
            #pragma unroll
            for (int i = 0; i < 4; i++)
                xv[i] = *(const float4*)(X + (size_t)(m0 + xrow) * C_DIM + k0 + 32 + xc0 + 4 * i);
            #pragma unroll
            for (int i = 0; i < 4; i++)
                wv[i] = *(const float4*)(W + (size_t)(k0 + 32 + wrow) * D_HEAD + wc0 + 4 * i);
        }

        #pragma unroll
        for (int kc = 0; kc < 4; kc++) {
            uint32_t a0 = fb(Xs[w*16 + g    ][kc*8 + tig    ]);
            uint32_t a1 = fb(Xs[w*16 + g + 8][kc*8 + tig    ]);
            uint32_t a2 = fb(Xs[w*16 + g    ][kc*8 + tig + 4]);
            uint32_t a3 = fb(Xs[w*16 + g + 8][kc*8 + tig + 4]);
            #pragma unroll
            for (int nt = 0; nt < 8; nt++) {
                uint32_t b0 = fb(Ws[kc*8 + tig    ][nt*8 + g]);
                uint32_t b1 = fb(Ws[kc*8 + tig + 4][nt*8 + g]);
                mma_tf32(c[nt], a0, a1, a2, a3, b0, b1);
            }
        }
        __syncthreads();
    }

    const int rlo = m0 + w*16 + g;
    const int rhi = rlo + 8;
    #pragma unroll
    for (int nt = 0; nt < 8; nt++) {
        int col = nt*8 + 2*tig;
        float b0 = bias[col], b1 = bias[col + 1];
        *(float2*)(out + (size_t)rlo * D_HEAD + col) =
            make_float2(__uint_as_float(f2tf((c[nt][0] + b0) * osc)),
                        __uint_as_float(f2tf((c[nt][1] + b1) * osc)));
        *(float2*)(out + (size_t)rhi * D_HEAD + col) =
            make_float2(__uint_as_float(f2tf((c[nt][2] + b0) * osc)),
                        __uint_as_float(f2tf((c[nt][3] + b1) * osc)));
    }
}

// ---------------------------------------------------------------------------
// Flash attention partial: 128-row q-tile, 256 threads (8 warps x 16 rows),
// split-KV chunks of <=8 k-tiles. K and V double-buffered via cp.async
// (one group per iter), dedicated P buffer -> ONE __syncthreads per iter.
// ---------------------------------------------------------------------------
#define KST 68
#define VST 72
#define PST 68
#define SMEM_ATTN ((2*64*KST + 2*64*VST + 128*PST) * 4)

__global__ __launch_bounds__(256, 2) void attn_partial_kernel()
{
    extern __shared__ float sm[];
    float* ks[2] = { sm, sm + 64*KST };
    float* vs[2] = { sm + 2*64*KST, sm + 2*64*KST + 64*VST };
    float* ps    = sm + 2*64*KST + 2*64*VST;   // [128][PST]

    const int b = blockIdx.y;
    int idx = NCTA_B - 1 - blockIdx.x;   // heavy q-tiles first
    int grp = 0, base = 0;
    while (idx >= base + 4*(grp+1)) { base += 4*(grp+1); ++grp; }
    int r  = idx - base;
    int qt = 4*grp + r / (grp+1);
    int ci = r % (grp+1);
    const int j0   = ci * CHUNK;
    const int jend = min(j0 + CHUNK, 2*qt + 2);

    const int t    = threadIdx.x;
    const int lane = t & 31;
    const int w    = t >> 5;          // 0..7
    const int g    = lane >> 2;
    const int tig  = lane & 3;
    const int rlo  = w*16 + g;        // local q row 0..127
    const int rhi  = rlo + 8;

    const float* qp = g_q + ((size_t)b * T_LEN + qt * 128) * D_HEAD;
    const float* kb = g_k + (size_t)b * T_LEN * D_HEAD;
    const float* vb = g_v + (size_t)b * T_LEN * D_HEAD;

    const int row = t >> 2;           // 0..63
    const int c0  = (t & 3) * 16;     // 0,16,32,48

    // Prologue: issue K_j0 + V_j0 as one group
    {
        const float* kp = kb + (size_t)(j0*64 + row) * D_HEAD + c0;
        const float* vp = vb + (size_t)(j0*64 + row) * D_HEAD + c0;
        #pragma unroll
        for (int i = 0; i < 4; i++) cp16(ks[0] + row*KST + c0 + 4*i, kp + 4*i);
        #pragma unroll
        for (int i = 0; i < 4; i++) cp16(vs[0] + row*VST + c0 + 4*i, vp + 4*i);
        CP_COMMIT();
    }

    // Q fragments: tf32 bits, pre-scaled by proj
    uint32_t qa[8][4];
    #pragma unroll
    for (int kc = 0; kc < 8; kc++) {
        qa[kc][0] = fb(qp[rlo * D_HEAD + kc*8 + tig    ]);
        qa[kc][1] = fb(qp[rhi * D_HEAD + kc*8 + tig    ]);
        qa[kc][2] = fb(qp[rlo * D_HEAD + kc*8 + tig + 4]);
        qa[kc][3] = fb(qp[rhi * D_HEAD + kc*8 + tig + 4]);
    }

    float oc[8][4] = {};
    float m_lo = -1e30f, m_hi = -1e30f, l_lo = 0.f, l_hi = 0.f;

    for (int j = j0; j < jend; j++) {
        const int bufc = (j - j0) & 1;
        float* kcur = ks[bufc];
        float* vcur = vs[bufc];
        float* knxt = ks[bufc ^ 1];
        float* vnxt = vs[bufc ^ 1];

        CP_WAIT(0);        // group j arrived (group j+1 not yet issued)
        __syncthreads();   // visibility to all warps + buffer-reuse safety

        if (j + 1 < jend) {
            const float* kp = kb + (size_t)((j+1)*64 + row) * D_HEAD + c0;
            const float* vp = vb + (size_t)((j+1)*64 + row) * D_HEAD + c0;
            #pragma unroll
            for (int i = 0; i < 4; i++) cp16(knxt + row*KST + c0 + 4*i, kp + 4*i);
            #pragma unroll
            for (int i = 0; i < 4; i++) cp16(vnxt + row*VST + c0 + 4*i, vp + 4*i);
            CP_COMMIT();
        }

        // S = Q @ K^T
        float sc[8][4] = {};
        #pragma unroll
        for (int kc = 0; kc < 8; kc++) {
            #pragma unroll
            for (int nt = 0; nt < 8; nt++) {
                uint32_t b0 = fb(kcur[(nt*8 + g)*KST + kc*8 + tig    ]);
                uint32_t b1 = fb(kcur[(nt*8 + g)*KST + kc*8 + tig + 4]);
                mma_tf32(sc[nt], qa[kc][0], qa[kc][1], qa[kc][2], qa[kc][3], b0, b1);
            }
        }

        // Causal mask: only k-tiles j >= 2*qt touch the diagonal
        if (j >= 2*qt) {
            const int co = (j - 2*qt) * 64;   // col offset rel. to q-tile start
            #pragma unroll
            for (int nt = 0; nt < 8; nt++) {
                int cb = co + nt*8 + 2*tig;
                if (cb     > rlo) sc[nt][0] = -1e30f;
                if (cb + 1 > rlo) sc[nt][1] = -1e30f;
                if (cb     > rhi) sc[nt][2] = -1e30f;
                if (cb + 1 > rhi) sc[nt][3] = -1e30f;
            }
        }

        // Online softmax (rows within warp; quad shuffles)
        float mx0 = -1e30f, mx1 = -1e30f;
        #pragma unroll
        for (int nt = 0; nt < 8; nt++) {
            mx0 = fmaxf(mx0, fmaxf(sc[nt][0], sc[nt][1]));
            mx1 = fmaxf(mx1, fmaxf(sc[nt][2], sc[nt][3]));
        }
        mx0 = fmaxf(mx0, __shfl_xor_sync(0xffffffffu, mx0, 1));
        mx0 = fmaxf(mx0, __shfl_xor_sync(0xffffffffu, mx0, 2));
        mx1 = fmaxf(mx1, __shfl_xor_sync(0xffffffffu, mx1, 1));
        mx1 = fmaxf(mx1, __shfl_xor_sync(0xffffffffu, mx1, 2));

        float mn0 = fmaxf(m_lo, mx0);
        float mn1 = fmaxf(m_hi, mx1);
        float s0 = 0.f, s1 = 0.f;
        #pragma unroll
        for (int nt = 0; nt < 8; nt++) {
            sc[nt][0] = __expf(sc[nt][0] - mn0); s0 += sc[nt][0];
            sc[nt][1] = __expf(sc[nt][1] - mn0); s0 += sc[nt][1];
            sc[nt][2] = __expf(sc[nt][2] - mn1); s1 += sc[nt][2];
            sc[nt][3] = __expf(sc[nt][3] - mn1); s1 += sc[nt][3];
        }
        s0 += __shfl_xor_sync(0xffffffffu, s0, 1);
        s0 += __shfl_xor_sync(0xffffffffu, s0, 2);
        s1 += __shfl_xor_sync(0xffffffffu, s1, 1);
        s1 += __shfl_xor_sync(0xffffffffu, s1, 2);

        float a0 = __expf(m_lo - mn0);
        float a1 = __expf(m_hi - mn1);
        l_lo = l_lo * a0 + s0;  m_lo = mn0;
        l_hi = l_hi * a1 + s1;  m_hi = mn1;
        #pragma unroll
        for (int nt = 0; nt < 8; nt++) {
            oc[nt][0] *= a0; oc[nt][1] *= a0;
            oc[nt][2] *= a1; oc[nt][3] *= a1;
        }

        // P -> ps rows [w*16, w*16+16) (per-warp private strip)
        {
            float* plo = ps + rlo*PST;
            float* phi = ps + rhi*PST;
            #pragma unroll
            for (int nt = 0; nt < 8; nt++) {
                int cb = nt*8 + 2*tig;
                *(float2*)&plo[cb] = make_float2(__uint_as_float(f2tf(sc[nt][0])),
                                                 __uint_as_float(f2tf(sc[nt][1])));
                *(float2*)&phi[cb] = make_float2(__uint_as_float(f2tf(sc[nt][2])),
                                                 __uint_as_float(f2tf(sc[nt][3])));
            }
        }
        __syncwarp();

        // O += P @ V
        #pragma unroll
        for (int kc = 0; kc < 8; kc++) {
            uint32_t pa0 = fb(ps[rlo*PST + kc*8 + tig    ]);
            uint32_t pa1 = fb(ps[rhi*PST + kc*8 + tig    ]);
            uint32_t pa2 = fb(ps[rlo*PST + kc*8 + tig + 4]);
            uint32_t pa3 = fb(ps[rhi*PST + kc*8 + tig + 4]);
            #pragma unroll
            for (int nt = 0; nt < 8; nt++) {
                uint32_t b0 = fb(vcur[(kc*8 + tig    )*VST + nt*8 + g]);
                uint32_t b1 = fb(vcur[(kc*8 + tig + 4)*VST + nt*8 + g]);
                mma_tf32(oc[nt], pa0, pa1, pa2, pa3, b0, b1);
            }
        }
    }

    // Write partial (unnormalized) + m/l
    const size_t pbase = ((size_t)(b * NQT + qt) * MAXCH + ci);
    float* pO = g_pO + pbase * 128 * 64;
    #pragma unroll
    for (int nt = 0; nt < 8; nt++) {
        int col = nt*8 + 2*tig;
        *(float2*)(pO + rlo * 64 + col) = make_float2(oc[nt][0], oc[nt][1]);
        *(float2*)(pO + rhi * 64 + col) = make_float2(oc[nt][2], oc[nt][3]);
    }
    if (tig == 0) {
        g_pm[pbase * 128 + rlo] = m_lo;
        g_pm[pbase * 128 + rhi] = m_hi;
        g_pl[pbase * 128 + rlo] = l_lo;
        g_pl[pbase * 128 + rhi] = l_hi;
    }
}

// ---------------------------------------------------------------------------
// Merge: combine <=8 partials per 128-row q-tile (log-sum-exp), normalize.
// Grid (NQT, B), block 256: thread -> (row = t>>1, 32 cols).
// ---------------------------------------------------------------------------
__global__ __launch_bounds__(256) void attn_merge_kernel(float* __restrict__ out)
{
    const int qt = blockIdx.x;
    const int b  = blockIdx.y;
    const int nc = qt / 4 + 1;

    const int t   = threadIdx.x;
    const int row = t >> 1;          // 0..127
    const int c0  = (t & 1) * 32;

    const size_t pbase = (size_t)(b * NQT + qt) * MAXCH;

    float mv[MAXCH], lv[MAXCH];
    float M = -1e30f;
    for (int ci = 0; ci < nc; ci++) {
        mv[ci] = g_pm[(pbase + ci) * 128 + row];
        lv[ci] = g_pl[(pbase + ci) * 128 + row];
        M = fmaxf(M, mv[ci]);
    }
    float L = 0.f;
    for (int ci = 0; ci < nc; ci++) L += lv[ci] * __expf(mv[ci] - M);

    float acc[32] = {};
    for (int ci = 0; ci < nc; ci++) {
        float wgt = __expf(mv[ci] - M);
        const float* pO = g_pO + (pbase + ci) * 128 * 64 + row * 64 + c0;
        #pragma unroll
        for (int u = 0; u < 8; u++) {
            float4 v4 = *(const float4*)(pO + 4*u);
            acc[4*u + 0] += wgt * v4.x;
            acc[4*u + 1] += wgt * v4.y;
            acc[4*u + 2] += wgt * v4.z;
            acc[4*u + 3] += wgt * v4.w;
        }
    }
    float inv = 1.0f / L;
    float* ob = out + ((size_t)b * T_LEN + qt * 128 + row) * D_HEAD + c0;
    #pragma unroll
    for (int u = 0; u < 8; u++)
        *(float4*)(ob + 4*u) = make_float4(acc[4*u + 0] * inv, acc[4*u + 1] * inv,
                                           acc[4*u + 2] * inv, acc[4*u + 3] * inv);
}

// ---------------------------------------------------------------------------
extern "C" void kernel_launch(void* const* d_in, const int* in_sizes, int n_in,
                              void* d_out, int out_size)
{
    (void)in_sizes; (void)n_in; (void)out_size;
    const float* Q  = (const float*)d_in[0];
    const float* K  = (const float*)d_in[1];
    const float* V  = (const float*)d_in[2];
    const float* Wq = (const float*)d_in[3];
    const float* bq = (const float*)d_in[4];
    const float* Wk = (const float*)d_in[5];
    const float* bk = (const float*)d_in[6];
    const float* Wv = (const float*)d_in[7];
    const float* bv = (const float*)d_in[8];

    static bool attr_set = false;
    if (!attr_set) {
        cudaFuncSetAttribute(attn_partial_kernel,
                             cudaFuncAttributeMaxDynamicSharedMemorySize, SMEM_ATTN);
        attr_set = true;
    }

    dim3 pg(M_ROWS / 64, 3);
    proj_kernel<<<pg, 128>>>(Q, K, V, Wq, bq, Wk, bk, Wv, bv);

    dim3 ag(NCTA_B, B_SZ);
    attn_partial_kernel<<<ag, 256, SMEM_ATTN>>>();

    dim3 mg(NQT, B_SZ);
    attn_merge_kernel<<<mg, 256>>>((float*)d_out);
}